// round 6
// baseline (speedup 1.0000x reference)
#include <cuda_runtime.h>
#include <cuda_fp16.h>
#include <cstdint>
#include <cstddef>

// Problem dims
#define BB    64
#define CC    512
#define HWS   784
#define MTOT  (BB * HWS)        // 50176
#define MTILE 128
#define NTILE 256
#define KCH   64                // K chunk
#define NCHNK (CC / KCH)        // 8

// smem: 2 stages x { A[64k][256B] 16384 + B[256n][128B] 32768 } = 98304
// params at 98304: 5 x 256 + 512 (rb) f32 = 7168 -> total 105472 (2 CTAs/SM)
// epilogue D-half tile (128 x 129 f32 = 66048B) reuses stage area
#define ASZ      16384u
#define STAGEB   49152u
#define SMPAR    98304u
#define SMTOTAL  105472u
#define TPITCH   129

// ---------------- scratch ----------------
__device__ __half g_wb[CC * CC];            // sign(W) [N][K], +-1 fp16
__device__ float g_alpha[CC];
__device__ float g_beta2[CC];

// ---------------- helpers ----------------
static __device__ __forceinline__ uint32_t smem_u32(const void* p) {
    uint32_t a;
    asm("{ .reg .u64 t; cvta.to.shared.u64 t, %1; cvt.u32.u64 %0, t; }" : "=r"(a) : "l"(p));
    return a;
}
static __device__ __forceinline__ void cp16(uint32_t s, const void* g) {
    asm volatile("cp.async.cg.shared.global [%0], [%1], 16;" :: "r"(s), "l"(g) : "memory");
}
#define CP_COMMIT() asm volatile("cp.async.commit_group;" ::: "memory")
#define CP_WAIT(n)  asm volatile("cp.async.wait_group %0;" :: "n"(n) : "memory")

static __device__ __forceinline__ void ldsm4(uint32_t* r, uint32_t a) {
    asm volatile("ldmatrix.sync.aligned.m8n8.x4.shared.b16 {%0,%1,%2,%3}, [%4];"
                 : "=r"(r[0]), "=r"(r[1]), "=r"(r[2]), "=r"(r[3]) : "r"(a));
}
static __device__ __forceinline__ void ldsm4t(uint32_t* r, uint32_t a) {
    asm volatile("ldmatrix.sync.aligned.m8n8.x4.trans.shared.b16 {%0,%1,%2,%3}, [%4];"
                 : "=r"(r[0]), "=r"(r[1]), "=r"(r[2]), "=r"(r[3]) : "r"(a));
}
static __device__ __forceinline__ void sts128(uint32_t a, uint32_t x0, uint32_t x1,
                                              uint32_t x2, uint32_t x3) {
    asm volatile("st.shared.v4.b32 [%0], {%1,%2,%3,%4};"
                 :: "r"(a), "r"(x0), "r"(x1), "r"(x2), "r"(x3) : "memory");
}
static __device__ __forceinline__ void mma_h(uint32_t* c, const uint32_t* a,
                                             uint32_t b0, uint32_t b1) {
    asm volatile(
        "mma.sync.aligned.m16n8k16.row.col.f16.f16.f16.f16 "
        "{%0,%1}, {%2,%3,%4,%5}, {%6,%7}, {%0,%1};"
        : "+r"(c[0]), "+r"(c[1])
        : "r"(a[0]), "r"(a[1]), "r"(a[2]), "r"(a[3]), "r"(b0), "r"(b1));
}
// B-tile swizzle: 128B rows
static __device__ __forceinline__ uint32_t swzB(int row, int seg) {
    return (uint32_t)(row * 128 + ((seg ^ (row & 7)) << 4));
}
// pack two (x+bias) floats into fp16x2 of +-1
static __device__ __forceinline__ uint32_t pack2(float a, float b) {
    uint32_t ua = __float_as_uint(a), ub = __float_as_uint(b);
    return 0x3C003C00u | ((ua >> 16) & 0x8000u) | (ub & 0x80000000u);
}

// ---------------- kernel 1: epilogue constants ----------------
__global__ void prep_kernel(const float* __restrict__ W, const float* __restrict__ gam,
                            const float* __restrict__ bet, const float* __restrict__ mea,
                            const float* __restrict__ var) {
    int wid = threadIdx.x >> 5, lane = threadIdx.x & 31;
    int o = blockIdx.x * 8 + wid;
    const float* wr = W + (size_t)o * CC;
    float s = 0.f;
    #pragma unroll
    for (int j = 0; j < 16; j++) s += fabsf(wr[lane + j * 32]);
    #pragma unroll
    for (int off = 16; off > 0; off >>= 1) s += __shfl_xor_sync(0xffffffffu, s, off);
    if (lane == 0) {
        float scale = s * (1.0f / 512.0f);
        float A = gam[o] * rsqrtf(var[o] + 1e-5f);
        g_alpha[o] = A * scale;
        g_beta2[o] = bet[o] - A * mea[o];
    }
}

// ---------------- kernel 2: Wb = sign(W) as fp16 (+-1) ----------------
__global__ void sign_w_kernel(const float* __restrict__ W) {
    int i = blockIdx.x * blockDim.x + threadIdx.x;
    float2 v = reinterpret_cast<const float2*>(W)[i];
    uint32_t p = ((v.x >= 0.f) ? 0x3C00u : 0xBC00u) |
                 (((v.y >= 0.f) ? 0x3C00u : 0xBC00u) << 16);
    reinterpret_cast<uint32_t*>(g_wb)[i] = p;
}

// ---------------- kernel 3: fused binarize + fp16 mma GEMM + epilogue ----------------
__global__ void __launch_bounds__(256, 2)
gemm_kernel(const float* __restrict__ x, const float* __restrict__ rb,
            const float* __restrict__ slope, const float* __restrict__ shift,
            const float* __restrict__ pbias, float* __restrict__ out)
{
    extern __shared__ char smem[];
    const uint32_t sb = smem_u32(smem);
    const int tid = threadIdx.x, wid = tid >> 5, lane = tid & 31;
    const int m0 = blockIdx.y * MTILE;
    const int n0 = blockIdx.x * NTILE;

    float* alphaS = reinterpret_cast<float*>(smem + SMPAR);
    float* betaS  = alphaS + 256;
    float* slopeS = alphaS + 512;
    float* shiftS = alphaS + 768;
    float* pbiasS = alphaS + 1024;
    float* rbS    = alphaS + 1280;           // 512 entries
    alphaS[tid] = g_alpha[n0 + tid];
    betaS[tid]  = g_beta2[n0 + tid];
    slopeS[tid] = slope[n0 + tid];
    shiftS[tid] = shift[n0 + tid];
    pbiasS[tid] = pbias[n0 + tid];
    rbS[tid]       = rb[tid];
    rbS[tid + 256] = rb[tid + 256];
    __syncthreads();   // rbS is read cross-thread in the prologue below (R5 bug fix)

    // ---- B loader (cp.async) ----
    const int ldrow = tid >> 3;           // 0..31
    const int ldseg = tid & 7;
    auto loadB = [&](int c, int st) {
        const uint32_t so = sb + (uint32_t)st * STAGEB + ASZ;
        const char* gb = (const char*)g_wb + ((size_t)n0 * CC + c * KCH) * 2;
        #pragma unroll
        for (int j = 0; j < 8; j++) {
            int row = ldrow + j * 32;
            cp16(so + swzB(row, ldseg), gb + (size_t)row * (CC * 2) + ldseg * 16);
        }
        CP_COMMIT();
    };

    // ---- A loader thread mapping: kk = wid*8 + (lane&7), q = lane>>3 ----
    const int kkl = lane & 7;
    const int kk  = wid * 8 + kkl;        // 0..63 (k row within chunk)
    const int q   = lane >> 3;            // m quarter (32 m each)
    const int mBase = m0 + q * 32;
    const int bB  = mBase / HWS;
    const int hwB = mBase - bB * HWS;
    const int cross = HWS - hwB;          // split offset within 32-m window (if <32)

    // load 4 consecutive m at offset 'off' for channel pointer pair
    auto ldg4 = [&](const float* p0, const float* p1, int off) -> float4 {
        if (off + 4 <= cross) return *reinterpret_cast<const float4*>(p0 + off);
        if (off >= cross)     return *reinterpret_cast<const float4*>(p1 + off);
        float4 v;
        v.x = (off     >= cross ? p1 : p0)[off];
        v.y = (off + 1 >= cross ? p1 : p0)[off + 1];
        v.z = (off + 2 >= cross ? p1 : p0)[off + 2];
        v.w = (off + 3 >= cross ? p1 : p0)[off + 3];
        return v;
    };

    // mma fragment addressing
    const int mw = (wid >> 2) * 64;       // warp row: 0/64
    const int nw = (wid & 3) * 64;        // warp col
    const int aKl   = (lane & 7) + ((lane >> 4) & 1) * 8;   // k within 16
    const int aMsel = (lane >> 3) & 1;                       // +8 m (seg +1)
    const int bRowSel = (lane & 7) + ((lane >> 3) & 1) * 8;
    const int bSegHi  = (lane >> 4) & 1;

    // ---- prologue: stage 0 ----
    loadB(0, 0);
    {
        const float* p0 = x + ((size_t)bB * CC + kk) * HWS + hwB;
        const float* p1 = p0 + (size_t)CC * HWS - HWS;
        const float rbv = rbS[kk];
        uint32_t pk[16];
        #pragma unroll
        for (int j = 0; j < 8; j++) {
            float4 v = ldg4(p0, p1, j * 4);
            pk[2 * j]     = pack2(v.x + rbv, v.y + rbv);
            pk[2 * j + 1] = pack2(v.z + rbv, v.w + rbv);
        }
        const uint32_t ab = sb + (uint32_t)kk * 256u;
        #pragma unroll
        for (int t = 0; t < 4; t++)
            sts128(ab + ((uint32_t)((q * 4 + t) ^ kkl) << 4),
                   pk[4 * t], pk[4 * t + 1], pk[4 * t + 2], pk[4 * t + 3]);
    }
    CP_WAIT(0);
    __syncthreads();

    uint32_t acc[4][8][2] = {};

    #pragma unroll 2
    for (int c = 0; c < NCHNK; c++) {
        const int st = c & 1;
        const uint32_t aBase = sb + (uint32_t)st * STAGEB;
        const uint32_t bBase = aBase + ASZ;
        if (c + 1 < NCHNK) loadB(c + 1, st ^ 1);

        const int kg = (c + 1) * KCH + kk;               // next chunk's channel
        const float* p0 = x + ((size_t)bB * CC + kg) * HWS + hwB;
        const float* p1 = p0 + (size_t)CC * HWS - HWS;
        float4 va[4], vb[4];
        uint32_t pk[16];

        // helper: one ks step of mma
        auto mma_ks = [&](int ks) {
            const int kbase = ks * 16;
            uint32_t af[4][4], bf[4][4];
            #pragma unroll
            for (int mt = 0; mt < 4; mt++) {
                int kloc = kbase + aKl;
                int mseg = ((mw + mt * 16) >> 3) + aMsel;
                ldsm4t(af[mt], aBase + kloc * 256 + ((uint32_t)(mseg ^ (kloc & 7)) << 4));
            }
            #pragma unroll
            for (int nt = 0; nt < 4; nt++) {
                int r = nw + nt * 16 + bRowSel;
                ldsm4(bf[nt], bBase + swzB(r, ks * 2 + bSegHi));
            }
            #pragma unroll
            for (int mt = 0; mt < 4; mt++) {
                #pragma unroll
                for (int nt = 0; nt < 4; nt++) {
                    mma_h(acc[mt][2 * nt],     af[mt], bf[nt][0], bf[nt][2]);
                    mma_h(acc[mt][2 * nt + 1], af[mt], bf[nt][1], bf[nt][3]);
                }
            }
        };

        mma_ks(0);
        if (c + 1 < NCHNK) {
            #pragma unroll
            for (int j = 0; j < 4; j++) va[j] = ldg4(p0, p1, j * 4);
        }
        mma_ks(1);
        if (c + 1 < NCHNK) {
            const float rbv = rbS[kg];
            #pragma unroll
            for (int j = 0; j < 4; j++) {
                pk[2 * j]     = pack2(va[j].x + rbv, va[j].y + rbv);
                pk[2 * j + 1] = pack2(va[j].z + rbv, va[j].w + rbv);
            }
            #pragma unroll
            for (int j = 0; j < 4; j++) vb[j] = ldg4(p0, p1, 16 + j * 4);
        }
        mma_ks(2);
        if (c + 1 < NCHNK) {
            const float rbv = rbS[kg];
            #pragma unroll
            for (int j = 0; j < 4; j++) {
                pk[8 + 2 * j] = pack2(vb[j].x + rbv, vb[j].y + rbv);
                pk[9 + 2 * j] = pack2(vb[j].z + rbv, vb[j].w + rbv);
            }
        }
        mma_ks(3);
        if (c + 1 < NCHNK) {
            const uint32_t ab = sb + (uint32_t)(st ^ 1) * STAGEB + (uint32_t)kk * 256u;
            #pragma unroll
            for (int t = 0; t < 4; t++)
                sts128(ab + ((uint32_t)((q * 4 + t) ^ kkl) << 4),
                       pk[4 * t], pk[4 * t + 1], pk[4 * t + 2], pk[4 * t + 3]);
            CP_WAIT(0);
        }
        __syncthreads();
    }

    // ---- epilogue: two 128-col halves staged through smem ----
    float* tile = reinterpret_cast<float*>(smem);
    const int dr = lane >> 2;
    const int dc = (lane & 3) * 2;
    const int myhalf = (wid & 3) >> 1;
    const int nlb = (wid & 1) * 64;

    #pragma unroll
    for (int h = 0; h < 2; h++) {
        if (myhalf == h) {
            #pragma unroll
            for (int mt = 0; mt < 4; mt++) {
                #pragma unroll
                for (int nt = 0; nt < 8; nt++) {
                    int r = mw + mt * 16 + dr;
                    int c2 = nlb + nt * 8 + dc;
                    float2 lo = __half22float2(*reinterpret_cast<__half2*>(&acc[mt][nt][0]));
                    float2 hi = __half22float2(*reinterpret_cast<__half2*>(&acc[mt][nt][1]));
                    tile[r * TPITCH + c2]           = lo.x;
                    tile[r * TPITCH + c2 + 1]       = lo.y;
                    tile[(r + 8) * TPITCH + c2]     = hi.x;
                    tile[(r + 8) * TPITCH + c2 + 1] = hi.y;
                }
            }
        }
        __syncthreads();

        #pragma unroll 4
        for (int g = 0; g < 16; g++) {
            const int nl = wid + 8 * g;
            const int p = h * 128 + nl;
            const int n = n0 + p;
            const float al = alphaS[p], be = betaS[p];
            const float sl = slopeS[p], sh = shiftS[p], pb = pbiasS[p];
            #pragma unroll
            for (int j = 0; j < 4; j++) {
                int ml = lane + 32 * j;
                int m = m0 + ml;
                int b = m / HWS;
                int hw = m - b * HWS;
                size_t gi = ((size_t)(b * CC + n)) * HWS + hw;
                float raw = tile[ml * TPITCH + nl];
                float sv = fmaf(al, raw, be) + x[gi];
                float t = sv - sh;
                out[gi] = ((t > 0.f) ? t : sl * t) + pb;
            }
        }
        __syncthreads();
    }
}

// ---------------- launch ----------------
extern "C" void kernel_launch(void* const* d_in, const int* in_sizes, int n_in,
                              void* d_out, int out_size) {
    const float* x   = (const float*)d_in[0];
    const float* rb  = (const float*)d_in[1];
    const float* W   = (const float*)d_in[2];
    const float* gam = (const float*)d_in[3];
    const float* bet = (const float*)d_in[4];
    const float* mea = (const float*)d_in[5];
    const float* var = (const float*)d_in[6];
    const float* slo = (const float*)d_in[7];
    const float* shi = (const float*)d_in[8];
    const float* pbi = (const float*)d_in[9];
    float* out = (float*)d_out;

    cudaFuncSetAttribute(gemm_kernel, cudaFuncAttributeMaxDynamicSharedMemorySize, SMTOTAL);

    prep_kernel<<<64, 256>>>(W, gam, bet, mea, var);
    sign_w_kernel<<<512, 256>>>(W);
    gemm_kernel<<<dim3(2, MTOT / MTILE), 256, SMTOTAL>>>(x, rb, slo, shi, pbi, out);
}

// round 7
// speedup vs baseline: 1.3408x; 1.3408x over previous
#include <cuda_runtime.h>
#include <cuda_fp16.h>
#include <cstdint>
#include <cstddef>

// Problem dims
#define BB    64
#define CC    512
#define HWS   784
#define MTOT  (BB * HWS)        // 50176
#define MTILE 128
#define NTILE 256
#define KCH   64                // K chunk
#define NCHNK (CC / KCH)        // 8

// smem: 2 stages x { A[64k][256B] 16384 + B[256n][128B] 32768 } = 98304
// params at 98304: 5 x 256 + 512 (rb) f32 = 7168 -> total 105472 (2 CTAs/SM)
// epilogue D-half tile (128 x 129 f32 = 66048B) reuses stage area
#define ASZ      16384u
#define STAGEB   49152u
#define SMPAR    98304u
#define SMTOTAL  105472u
#define TPITCH   129

// ---------------- scratch ----------------
__device__ __half g_wb[CC * CC];            // sign(W) [N][K], +-1 fp16
__device__ float g_alpha[CC];
__device__ float g_beta2[CC];

// ---------------- helpers ----------------
static __device__ __forceinline__ uint32_t smem_u32(const void* p) {
    uint32_t a;
    asm("{ .reg .u64 t; cvta.to.shared.u64 t, %1; cvt.u32.u64 %0, t; }" : "=r"(a) : "l"(p));
    return a;
}
static __device__ __forceinline__ void cp16(uint32_t s, const void* g) {
    asm volatile("cp.async.cg.shared.global [%0], [%1], 16;" :: "r"(s), "l"(g) : "memory");
}
#define CP_COMMIT() asm volatile("cp.async.commit_group;" ::: "memory")
#define CP_WAIT(n)  asm volatile("cp.async.wait_group %0;" :: "n"(n) : "memory")

static __device__ __forceinline__ void ldsm4(uint32_t* r, uint32_t a) {
    asm volatile("ldmatrix.sync.aligned.m8n8.x4.shared.b16 {%0,%1,%2,%3}, [%4];"
                 : "=r"(r[0]), "=r"(r[1]), "=r"(r[2]), "=r"(r[3]) : "r"(a));
}
static __device__ __forceinline__ void ldsm4t(uint32_t* r, uint32_t a) {
    asm volatile("ldmatrix.sync.aligned.m8n8.x4.trans.shared.b16 {%0,%1,%2,%3}, [%4];"
                 : "=r"(r[0]), "=r"(r[1]), "=r"(r[2]), "=r"(r[3]) : "r"(a));
}
static __device__ __forceinline__ void sts128(uint32_t a, uint32_t x0, uint32_t x1,
                                              uint32_t x2, uint32_t x3) {
    asm volatile("st.shared.v4.b32 [%0], {%1,%2,%3,%4};"
                 :: "r"(a), "r"(x0), "r"(x1), "r"(x2), "r"(x3) : "memory");
}
static __device__ __forceinline__ void mma_h(uint32_t* c, const uint32_t* a,
                                             uint32_t b0, uint32_t b1) {
    asm volatile(
        "mma.sync.aligned.m16n8k16.row.col.f16.f16.f16.f16 "
        "{%0,%1}, {%2,%3,%4,%5}, {%6,%7}, {%0,%1};"
        : "+r"(c[0]), "+r"(c[1])
        : "r"(a[0]), "r"(a[1]), "r"(a[2]), "r"(a[3]), "r"(b0), "r"(b1));
}
// B-tile swizzle: 128B rows
static __device__ __forceinline__ uint32_t swzB(int row, int seg) {
    return (uint32_t)(row * 128 + ((seg ^ (row & 7)) << 4));
}
// pack two (x+bias) floats into fp16x2 of +-1
static __device__ __forceinline__ uint32_t pack2(float a, float b) {
    uint32_t ua = __float_as_uint(a), ub = __float_as_uint(b);
    return 0x3C003C00u | ((ua >> 16) & 0x8000u) | (ub & 0x80000000u);
}

// ---------------- kernel 1: epilogue constants ----------------
__global__ void prep_kernel(const float* __restrict__ W, const float* __restrict__ gam,
                            const float* __restrict__ bet, const float* __restrict__ mea,
                            const float* __restrict__ var) {
    int wid = threadIdx.x >> 5, lane = threadIdx.x & 31;
    int o = blockIdx.x * 8 + wid;
    const float* wr = W + (size_t)o * CC;
    float s = 0.f;
    #pragma unroll
    for (int j = 0; j < 16; j++) s += fabsf(wr[lane + j * 32]);
    #pragma unroll
    for (int off = 16; off > 0; off >>= 1) s += __shfl_xor_sync(0xffffffffu, s, off);
    if (lane == 0) {
        float scale = s * (1.0f / 512.0f);
        float A = gam[o] * rsqrtf(var[o] + 1e-5f);
        g_alpha[o] = A * scale;
        g_beta2[o] = bet[o] - A * mea[o];
    }
}

// ---------------- kernel 2: Wb = sign(W) as fp16 (+-1) ----------------
__global__ void sign_w_kernel(const float* __restrict__ W) {
    int i = blockIdx.x * blockDim.x + threadIdx.x;
    float2 v = reinterpret_cast<const float2*>(W)[i];
    uint32_t p = ((v.x >= 0.f) ? 0x3C00u : 0xBC00u) |
                 (((v.y >= 0.f) ? 0x3C00u : 0xBC00u) << 16);
    reinterpret_cast<uint32_t*>(g_wb)[i] = p;
}

// ---------------- kernel 3: fused binarize + fp16 mma GEMM + epilogue ----------------
__global__ void __launch_bounds__(256, 2)
gemm_kernel(const float* __restrict__ x, const float* __restrict__ rb,
            const float* __restrict__ slope, const float* __restrict__ shift,
            const float* __restrict__ pbias, float* __restrict__ out)
{
    extern __shared__ char smem[];
    const uint32_t sb = smem_u32(smem);
    const int tid = threadIdx.x, wid = tid >> 5, lane = tid & 31;
    const int m0 = blockIdx.y * MTILE;
    const int n0 = blockIdx.x * NTILE;

    float* alphaS = reinterpret_cast<float*>(smem + SMPAR);
    float* betaS  = alphaS + 256;
    float* slopeS = alphaS + 512;
    float* shiftS = alphaS + 768;
    float* pbiasS = alphaS + 1024;
    float* rbS    = alphaS + 1280;           // 512 entries
    alphaS[tid] = g_alpha[n0 + tid];
    betaS[tid]  = g_beta2[n0 + tid];
    slopeS[tid] = slope[n0 + tid];
    shiftS[tid] = shift[n0 + tid];
    pbiasS[tid] = pbias[n0 + tid];
    rbS[tid]       = rb[tid];
    rbS[tid + 256] = rb[tid + 256];
    __syncthreads();   // rbS is read cross-thread below

    // ---- B loader (cp.async) ----
    const int ldrow = tid >> 3;           // 0..31
    const int ldseg = tid & 7;
    auto loadB = [&](int c, int st) {
        const uint32_t so = sb + (uint32_t)st * STAGEB + ASZ;
        const char* gb = (const char*)g_wb + ((size_t)n0 * CC + c * KCH) * 2;
        #pragma unroll
        for (int j = 0; j < 8; j++) {
            int row = ldrow + j * 32;
            cp16(so + swzB(row, ldseg), gb + (size_t)row * (CC * 2) + ldseg * 16);
        }
        CP_COMMIT();
    };

    // ---- A loader thread mapping: kk = wid*8 + (lane&7), q = lane>>3 ----
    const int kkl = lane & 7;
    const int kk  = wid * 8 + kkl;        // 0..63 (k row within chunk)
    const int q   = lane >> 3;            // m quarter (32 m each)
    const int mBase = m0 + q * 32;
    const int bB  = mBase / HWS;
    const int hwB = mBase - bB * HWS;
    const int cross = HWS - hwB;          // split offset within 32-m window (if <32)

    // load 4 consecutive m at offset 'off' for channel pointer pair
    auto ldg4 = [&](const float* p0, const float* p1, int off) -> float4 {
        if (off + 4 <= cross) return *reinterpret_cast<const float4*>(p0 + off);
        if (off >= cross)     return *reinterpret_cast<const float4*>(p1 + off);
        float4 v;
        v.x = (off     >= cross ? p1 : p0)[off];
        v.y = (off + 1 >= cross ? p1 : p0)[off + 1];
        v.z = (off + 2 >= cross ? p1 : p0)[off + 2];
        v.w = (off + 3 >= cross ? p1 : p0)[off + 3];
        return v;
    };

    // mma fragment addressing
    const int mw = (wid >> 2) * 64;       // warp row: 0/64
    const int nw = (wid & 3) * 64;        // warp col
    const int aKl   = (lane & 7) + ((lane >> 4) & 1) * 8;   // k within 16
    const int aMsel = (lane >> 3) & 1;                       // +8 m (seg +1)
    const int bRowSel = (lane & 7) + ((lane >> 3) & 1) * 8;
    const int bSegHi  = (lane >> 4) & 1;

    // ---- prologue: stage 0 (phased, low live regs) ----
    loadB(0, 0);
    {
        const float* p0 = x + ((size_t)bB * CC + kk) * HWS + hwB;
        const float* p1 = p0 + (size_t)CC * HWS - HWS;
        const float rbv = rbS[kk];
        const uint32_t ab = sb + (uint32_t)kk * 256u;
        #pragma unroll
        for (int p = 0; p < 4; p++) {
            float4 v0 = ldg4(p0, p1, p * 8);
            float4 v1 = ldg4(p0, p1, p * 8 + 4);
            sts128(ab + ((uint32_t)((q * 4 + p) ^ kkl) << 4),
                   pack2(v0.x + rbv, v0.y + rbv), pack2(v0.z + rbv, v0.w + rbv),
                   pack2(v1.x + rbv, v1.y + rbv), pack2(v1.z + rbv, v1.w + rbv));
        }
    }
    CP_WAIT(0);
    __syncthreads();

    uint32_t acc[4][8][2] = {};

    #pragma unroll 2
    for (int c = 0; c < NCHNK; c++) {
        const int st = c & 1;
        const uint32_t aBase = sb + (uint32_t)st * STAGEB;
        const uint32_t bBase = aBase + ASZ;
        const bool more = (c + 1 < NCHNK);
        if (more) loadB(c + 1, st ^ 1);

        const int kg = (c + 1) * KCH + kk;               // next chunk's channel
        const float* p0 = x + ((size_t)bB * CC + kg) * HWS + hwB;
        const float* p1 = p0 + (size_t)CC * HWS - HWS;
        const float rbv = more ? rbS[kg & 511] : 0.f;
        const uint32_t abN = sb + (uint32_t)(st ^ 1) * STAGEB + (uint32_t)kk * 256u;

        // one ks step of mma
        auto mma_ks = [&](int ks) {
            const int kbase = ks * 16;
            uint32_t af[4][4], bf[4][4];
            #pragma unroll
            for (int mt = 0; mt < 4; mt++) {
                int kloc = kbase + aKl;
                int mseg = ((mw + mt * 16) >> 3) + aMsel;
                ldsm4t(af[mt], aBase + kloc * 256 + ((uint32_t)(mseg ^ (kloc & 7)) << 4));
            }
            #pragma unroll
            for (int nt = 0; nt < 4; nt++) {
                int r = nw + nt * 16 + bRowSel;
                ldsm4(bf[nt], bBase + swzB(r, ks * 2 + bSegHi));
            }
            #pragma unroll
            for (int mt = 0; mt < 4; mt++) {
                #pragma unroll
                for (int nt = 0; nt < 4; nt++) {
                    mma_h(acc[mt][2 * nt],     af[mt], bf[nt][0], bf[nt][2]);
                    mma_h(acc[mt][2 * nt + 1], af[mt], bf[nt][1], bf[nt][3]);
                }
            }
        };

        // phased A production: load phase p before mma_ks(p), pack+STS after.
        float4 v0, v1;
        if (more) { v0 = ldg4(p0, p1, 0); v1 = ldg4(p0, p1, 4); }
        #pragma unroll
        for (int p = 0; p < 4; p++) {
            mma_ks(p);
            if (more) {
                uint32_t k0 = pack2(v0.x + rbv, v0.y + rbv);
                uint32_t k1 = pack2(v0.z + rbv, v0.w + rbv);
                uint32_t k2 = pack2(v1.x + rbv, v1.y + rbv);
                uint32_t k3 = pack2(v1.z + rbv, v1.w + rbv);
                sts128(abN + ((uint32_t)((q * 4 + p) ^ kkl) << 4), k0, k1, k2, k3);
                if (p < 3) {
                    v0 = ldg4(p0, p1, (p + 1) * 8);
                    v1 = ldg4(p0, p1, (p + 1) * 8 + 4);
                }
            }
        }
        if (more) CP_WAIT(0);
        __syncthreads();
    }

    // ---- epilogue: two 128-col halves staged through smem ----
    float* tile = reinterpret_cast<float*>(smem);
    const int dr = lane >> 2;
    const int dc = (lane & 3) * 2;
    const int myhalf = (wid & 3) >> 1;
    const int nlb = (wid & 1) * 64;

    #pragma unroll
    for (int h = 0; h < 2; h++) {
        if (myhalf == h) {
            #pragma unroll
            for (int mt = 0; mt < 4; mt++) {
                #pragma unroll
                for (int nt = 0; nt < 8; nt++) {
                    int r = mw + mt * 16 + dr;
                    int c2 = nlb + nt * 8 + dc;
                    float2 lo = __half22float2(*reinterpret_cast<__half2*>(&acc[mt][nt][0]));
                    float2 hi = __half22float2(*reinterpret_cast<__half2*>(&acc[mt][nt][1]));
                    tile[r * TPITCH + c2]           = lo.x;
                    tile[r * TPITCH + c2 + 1]       = lo.y;
                    tile[(r + 8) * TPITCH + c2]     = hi.x;
                    tile[(r + 8) * TPITCH + c2 + 1] = hi.y;
                }
            }
        }
        __syncthreads();

        #pragma unroll 4
        for (int g = 0; g < 16; g++) {
            const int nl = wid + 8 * g;
            const int p = h * 128 + nl;
            const int n = n0 + p;
            const float al = alphaS[p], be = betaS[p];
            const float sl = slopeS[p], sh = shiftS[p], pb = pbiasS[p];
            #pragma unroll
            for (int j = 0; j < 4; j++) {
                int ml = lane + 32 * j;
                int m = m0 + ml;
                int b = m / HWS;
                int hw = m - b * HWS;
                size_t gi = ((size_t)(b * CC + n)) * HWS + hw;
                float raw = tile[ml * TPITCH + nl];
                float sv = fmaf(al, raw, be) + x[gi];
                float t = sv - sh;
                out[gi] = ((t > 0.f) ? t : sl * t) + pb;
            }
        }
        __syncthreads();
    }
}

// ---------------- launch ----------------
extern "C" void kernel_launch(void* const* d_in, const int* in_sizes, int n_in,
                              void* d_out, int out_size) {
    const float* x   = (const float*)d_in[0];
    const float* rb  = (const float*)d_in[1];
    const float* W   = (const float*)d_in[2];
    const float* gam = (const float*)d_in[3];
    const float* bet = (const float*)d_in[4];
    const float* mea = (const float*)d_in[5];
    const float* var = (const float*)d_in[6];
    const float* slo = (const float*)d_in[7];
    const float* shi = (const float*)d_in[8];
    const float* pbi = (const float*)d_in[9];
    float* out = (float*)d_out;

    cudaFuncSetAttribute(gemm_kernel, cudaFuncAttributeMaxDynamicSharedMemorySize, SMTOTAL);

    prep_kernel<<<64, 256>>>(W, gam, bet, mea, var);
    sign_w_kernel<<<512, 256>>>(W);
    gemm_kernel<<<dim3(2, MTOT / MTILE), 256, SMTOTAL>>>(x, rb, slo, shi, pbi, out);
}